// round 2
// baseline (speedup 1.0000x reference)
#include <cuda_runtime.h>
#include <cstdint>
#include <cstddef>

#define N_JOBS 100000
#define N_MACH 10000
#define DIM 128
#define KDIM 256
#define BM 64
#define LN_EPS 1e-5f

// Scratch (no allocations allowed) — ~57 MB device globals.
__device__ __align__(256) float g_job_agg[(size_t)N_JOBS * DIM];
__device__ __align__(256) float g_mach_agg[(size_t)N_MACH * DIM];
__device__ __align__(256) float g_job_deg[N_JOBS];
__device__ __align__(256) float g_mach_deg[N_MACH];

__global__ void zero_kernel() {
    int i = blockIdx.x * blockDim.x + threadIdx.x;
    int stride = gridDim.x * blockDim.x;
    float4 z = make_float4(0.f, 0.f, 0.f, 0.f);
    for (int t = i; t < N_JOBS * DIM / 4; t += stride) ((float4*)g_job_agg)[t] = z;
    for (int t = i; t < N_MACH * DIM / 4; t += stride) ((float4*)g_mach_agg)[t] = z;
    for (int t = i; t < N_JOBS; t += stride) g_job_deg[t] = 0.f;
    for (int t = i; t < N_MACH; t += stride) g_mach_deg[t] = 0.f;
}

// One warp per edge, grid-stride over edges: 32 lanes x float4 = 128 floats.
// Both directions in one pass. Gathers hit L2-resident tables; scatters use
// vectorized red.global.add.v4.f32 (4x fewer RED ops than scalar).
__global__ void edge_kernel(const float* __restrict__ job_h,
                            const float* __restrict__ machine_h,
                            const int* __restrict__ job_idx,
                            const int* __restrict__ machine_idx,
                            int n_edges)
{
    int warp0 = (blockIdx.x * blockDim.x + threadIdx.x) >> 5;
    int nwarps = (gridDim.x * blockDim.x) >> 5;
    int lane = threadIdx.x & 31;
    int c = lane << 2;
    for (int e = warp0; e < n_edges; e += nwarps) {
        int j = __ldg(job_idx + e);
        int m = __ldg(machine_idx + e);
        float4 mh = *(const float4*)(machine_h + (size_t)m * DIM + c);
        float4 jh = *(const float4*)(job_h + (size_t)j * DIM + c);
        float* pj = g_job_agg + (size_t)j * DIM + c;
        float* pm = g_mach_agg + (size_t)m * DIM + c;
        asm volatile("red.global.add.v4.f32 [%0], {%1,%2,%3,%4};"
                     :: "l"(pj), "f"(mh.x), "f"(mh.y), "f"(mh.z), "f"(mh.w) : "memory");
        asm volatile("red.global.add.v4.f32 [%0], {%1,%2,%3,%4};"
                     :: "l"(pm), "f"(jh.x), "f"(jh.y), "f"(jh.z), "f"(jh.w) : "memory");
        if (lane == 0) {
            atomicAdd(g_job_deg + j, 1.0f);
            atomicAdd(g_mach_deg + m, 1.0f);
        }
    }
}

// Fused: X = [h | agg/deg] (BM x 256), Y = relu(X @ W^T + b), out = LayerNorm(Y).
// W (128x256) transposed into shared as Wt[k][o] with XOR swizzle (conflict-free
// LDS.64 b-loads). X tile in shared, a-loads are warp-broadcast LDS.128.
// Inner product uses packed fma.rn.f32x2 (2 fp32 FMA/instr).
// Thread map: warp tr=tid>>5 owns rows tr*8..tr*8+7; lane tc owns cols tc*4..tc*4+3.
// Each output row lives entirely in one warp -> LN via shfl reduction.
__global__ __launch_bounds__(256, 1) void fused_kernel(
    const float* __restrict__ h,
    const float* __restrict__ W,      // [128][256]
    const float* __restrict__ bias,   // [128]
    const float* __restrict__ ln_s,
    const float* __restrict__ ln_b,
    float* __restrict__ out,
    int n_rows, int mode)
{
    const float* agg = mode ? g_mach_agg : g_job_agg;
    const float* deg = mode ? g_mach_deg : g_job_deg;
    extern __shared__ float smem[];
    float* Wt = smem;                  // 256*128 floats (swizzled transpose)
    float* Xs = smem + KDIM * DIM;     // 64*256 floats
    int tid = threadIdx.x;
    int row0 = blockIdx.x * BM;

    // Load W -> shared, transposed + swizzled: element (k,o) at k*128 + (o ^ ((k>>2&7)<<2))
    #pragma unroll
    for (int it = 0; it < 32; it++) {
        int idx4 = tid + it * 256;          // over 8192 float4 of W
        int o = idx4 >> 6;
        int kb = (idx4 & 63) << 2;
        float4 w = *(const float4*)(W + o * KDIM + kb);
        int oo = o ^ (((kb >> 2) & 7) << 2);
        Wt[(kb + 0) * DIM + oo] = w.x;
        Wt[(kb + 1) * DIM + oo] = w.y;
        Wt[(kb + 2) * DIM + oo] = w.z;
        Wt[(kb + 3) * DIM + oo] = w.w;
    }

    // Load X tile: cols 0..127 from h, 128..255 from agg * 1/max(deg,1)
    #pragma unroll
    for (int it = 0; it < 16; it++) {
        int idx4 = tid + it * 256;          // over 4096 float4 of Xs
        int r = idx4 >> 6;
        int c = (idx4 & 63) << 2;
        int grow = row0 + r;
        float4 v = make_float4(0.f, 0.f, 0.f, 0.f);
        if (grow < n_rows) {
            if (c < DIM) {
                v = *(const float4*)(h + (size_t)grow * DIM + c);
            } else {
                float idg = 1.0f / fmaxf(deg[grow], 1.0f);
                float4 a = *(const float4*)(agg + (size_t)grow * DIM + (c - DIM));
                v.x = a.x * idg; v.y = a.y * idg; v.z = a.z * idg; v.w = a.w * idg;
            }
        }
        *(float4*)(Xs + r * KDIM + c) = v;
    }
    __syncthreads();

    int tc = tid & 31;
    int tr = tid >> 5;
    unsigned long long acc[8][2];           // f32x2 pairs: cols (4tc,4tc+1), (4tc+2,4tc+3)
    #pragma unroll
    for (int i = 0; i < 8; i++) { acc[i][0] = 0ull; acc[i][1] = 0ull; }

    const float* xrow = Xs + tr * 8 * KDIM;

    #pragma unroll 4
    for (int k0 = 0; k0 < KDIM; k0 += 4) {
        int s = (k0 >> 2) & 7;
        int ob = (tc ^ s) << 2;
        unsigned long long bq0[4], bq1[4];
        #pragma unroll
        for (int kk = 0; kk < 4; kk++) {
            const float* rp = Wt + (k0 + kk) * DIM + ob;
            bq0[kk] = *(const unsigned long long*)(rp);
            bq1[kk] = *(const unsigned long long*)(rp + 2);
        }
        #pragma unroll
        for (int i = 0; i < 8; i++) {
            float4 a = *(const float4*)(xrow + i * KDIM + k0);
            float av[4] = {a.x, a.y, a.z, a.w};
            #pragma unroll
            for (int kk = 0; kk < 4; kk++) {
                unsigned long long aa;
                asm("mov.b64 %0, {%1, %1};" : "=l"(aa) : "f"(av[kk]));
                asm("fma.rn.f32x2 %0, %1, %2, %0;" : "+l"(acc[i][0]) : "l"(aa), "l"(bq0[kk]));
                asm("fma.rn.f32x2 %0, %1, %2, %0;" : "+l"(acc[i][1]) : "l"(aa), "l"(bq1[kk]));
            }
        }
    }

    // Epilogue: +bias, relu, LayerNorm per row (row spread over one warp), store.
    float4 bb = *(const float4*)(bias + tc * 4);
    float4 gs = *(const float4*)(ln_s + tc * 4);
    float4 gb = *(const float4*)(ln_b + tc * 4);

    #pragma unroll
    for (int i = 0; i < 8; i++) {
        int grow = row0 + tr * 8 + i;
        float v0, v1, v2, v3;
        asm("mov.b64 {%0, %1}, %2;" : "=f"(v0), "=f"(v1) : "l"(acc[i][0]));
        asm("mov.b64 {%0, %1}, %2;" : "=f"(v2), "=f"(v3) : "l"(acc[i][1]));
        v0 = fmaxf(v0 + bb.x, 0.f);
        v1 = fmaxf(v1 + bb.y, 0.f);
        v2 = fmaxf(v2 + bb.z, 0.f);
        v3 = fmaxf(v3 + bb.w, 0.f);
        float sum = v0 + v1 + v2 + v3;
        float sq  = v0*v0 + v1*v1 + v2*v2 + v3*v3;
        #pragma unroll
        for (int off = 16; off > 0; off >>= 1) {
            sum += __shfl_xor_sync(0xffffffffu, sum, off);
            sq  += __shfl_xor_sync(0xffffffffu, sq,  off);
        }
        float mean = sum * (1.0f / 128.0f);
        float var  = sq * (1.0f / 128.0f) - mean * mean;
        float rstd = rsqrtf(var + LN_EPS);
        if (grow < n_rows) {
            float4 o;
            o.x = (v0 - mean) * rstd * gs.x + gb.x;
            o.y = (v1 - mean) * rstd * gs.y + gb.y;
            o.z = (v2 - mean) * rstd * gs.z + gb.z;
            o.w = (v3 - mean) * rstd * gs.w + gb.w;
            *(float4*)(out + (size_t)grow * DIM + tc * 4) = o;
        }
    }
}

extern "C" void kernel_launch(void* const* d_in, const int* in_sizes, int n_in,
                              void* d_out, int out_size)
{
    const float* job_h     = (const float*)d_in[0];
    const float* machine_h = (const float*)d_in[1];
    const float* W_job_w   = (const float*)d_in[2];
    const float* W_job_b   = (const float*)d_in[3];
    const float* W_mach_w  = (const float*)d_in[4];
    const float* W_mach_b  = (const float*)d_in[5];
    const float* lnj_s     = (const float*)d_in[6];
    const float* lnj_b     = (const float*)d_in[7];
    const float* lnm_s     = (const float*)d_in[8];
    const float* lnm_b     = (const float*)d_in[9];
    const int*   job_idx   = (const int*)d_in[10];
    const int*   mach_idx  = (const int*)d_in[11];
    float* out = (float*)d_out;
    int n_edges = in_sizes[10];

    const int smem_bytes = (KDIM * DIM + BM * KDIM) * (int)sizeof(float);  // 196608
    cudaFuncSetAttribute(fused_kernel, cudaFuncAttributeMaxDynamicSharedMemorySize, smem_bytes);

    zero_kernel<<<512, 256>>>();

    // 148 SMs * 16 blocks of 256 threads = grid-stride warps over 1.6M edges
    edge_kernel<<<148 * 16, 256>>>(job_h, machine_h, job_idx, mach_idx, n_edges);

    fused_kernel<<<(N_JOBS + BM - 1) / BM, 256, smem_bytes>>>(
        job_h, W_job_w, W_job_b, lnj_s, lnj_b, out, N_JOBS, 0);
    fused_kernel<<<(N_MACH + BM - 1) / BM, 256, smem_bytes>>>(
        machine_h, W_mach_w, W_mach_b, lnm_s, lnm_b, out + (size_t)N_JOBS * DIM, N_MACH, 1);
}